// round 11
// baseline (speedup 1.0000x reference)
#include <cuda_runtime.h>
#include <math.h>

// Problem constants
#define BB   4
#define CIN  32
#define CH   64
#define HH   24
#define WW   24
#define HWN  576          // 24*24
#define TT   5
#define DK   32
#define DV   32
#define NHN  4
#define GG   4
#define HEADS 64          // B*G*NH
#define TKEYS 2880        // T*HW
#define KC    9           // key chunks
#define KPC   320         // keys per chunk

// ---------------- scratch (device globals; no allocation allowed) -------------
__device__ float  g_xg[BB*GG*CH*HWN];        // conv on inputs, 4 gates x 64 ch
__device__ float  g_co[BB*GG*(CH-DV)*HWN];   // conv on rep, 4 gates x 32 ch
__device__ float4 g_q[HEADS*HWN*2];          // Q [head][q][8] (scaled by log2e/sqrt8)
__device__ float4 g_K[HEADS*TKEYS*2];        // K [head][j][8]
__device__ float4 g_V[HEADS*TKEYS*2];        // V [head][j][8]
__device__ float  g_L[KC*HEADS*HWN];         // partial exp-sums
__device__ float4 g_A[KC*HEADS*HWN*2];       // partial weighted V sums
__device__ float  g_attnp[BB*GG*DV*HWN];     // projected attention

__device__ __forceinline__ float ex2f(float x) {
    float r; asm("ex2.approx.ftz.f32 %0,%1;" : "=f"(r) : "f"(x)); return r;
}

// ---------------- KV projection, register-tiled, 640 blocks -------------------
__global__ __launch_bounds__(288)
void kv_tiled_kernel(const float* __restrict__ hist, // [B][T][CH][HW]
                     const float* __restrict__ kvw,  // [G][DK+DV][CH]
                     const float* __restrict__ kvb)  // [G][DK+DV]
{
    const int t    = blockIdx.x >> 2;
    const int pc   = blockIdx.x & 3;
    const int b    = blockIdx.y >> 2;
    const int g    = blockIdx.y & 3;
    const int half = blockIdx.z;
    const int tid  = threadIdx.x;
    const int og   = tid & 3;
    const int pg   = tid >> 2;          // 0..71

    __shared__ float wt[CH*32];         // [c][e] transposed
    __shared__ float bs[32];
    for (int i = tid; i < CH*32; i += 288) {
        int e = i & 31, c = i >> 5;
        wt[c*32 + e] = kvw[(g*(DK+DV) + half*32 + e)*CH + c];
    }
    if (tid < 32) bs[tid] = kvb[g*(DK+DV) + half*32 + tid];
    __syncthreads();

    float acc[8][2];
    #pragma unroll
    for (int o = 0; o < 8; o++) { acc[o][0] = 0.f; acc[o][1] = 0.f; }

    const int pxbase = pc*144 + pg*2;
    const float* hb = hist + ((b*TT + t)*CH)*HWN + pxbase;
    #pragma unroll 4
    for (int c = 0; c < CH; c++) {
        float2 px = *(const float2*)(hb + c*HWN);
        float4 w0 = *(const float4*)(&wt[c*32 + og*8]);
        float4 w1 = *(const float4*)(&wt[c*32 + og*8 + 4]);
        float wv[8] = {w0.x, w0.y, w0.z, w0.w, w1.x, w1.y, w1.z, w1.w};
        #pragma unroll
        for (int o = 0; o < 8; o++) {
            acc[o][0] = fmaf(wv[o], px.x, acc[o][0]);
            acc[o][1] = fmaf(wv[o], px.y, acc[o][1]);
        }
    }

    const int head = (b*GG + g)*NHN + og;
    float4* dst = (half == 0) ? g_K : g_V;
    float bb[8];
    #pragma unroll
    for (int o = 0; o < 8; o++) bb[o] = bs[og*8 + o];
    #pragma unroll
    for (int p = 0; p < 2; p++) {
        int j = t*HWN + pxbase + p;
        dst[(head*TKEYS + j)*2    ] = make_float4(acc[0][p]+bb[0], acc[1][p]+bb[1],
                                                  acc[2][p]+bb[2], acc[3][p]+bb[3]);
        dst[(head*TKEYS + j)*2 + 1] = make_float4(acc[4][p]+bb[4], acc[5][p]+bb[5],
                                                  acc[6][p]+bb[6], acc[7][p]+bb[7]);
    }
}

// ---------------- Q projection, 288-thread blocks, scale folds log2e ---------
__global__ __launch_bounds__(288)
void q_tiled_kernel(const float* __restrict__ rep,  // [B][CH][HW]
                    const float* __restrict__ qw,   // [G][DK][CH]
                    const float* __restrict__ qb)   // [G][DK]
{
    const int b     = blockIdx.x >> 2;
    const int g     = blockIdx.x & 3;
    const int chunk = blockIdx.y;       // 4 chunks of 144 px
    const int tid   = threadIdx.x;
    const int og    = tid & 3;
    const int pg    = tid >> 2;         // 0..71
    const int px0   = chunk*144 + pg*2;

    __shared__ float wt[CH*32];
    __shared__ float bs[32];
    for (int i = tid; i < CH*32; i += 288) {
        int e = i & 31, c = i >> 5;
        wt[c*32 + e] = qw[(g*DK + e)*CH + c];
    }
    if (tid < 32) bs[tid] = qb[g*DK + tid];
    __syncthreads();

    float acc[8][2];
    #pragma unroll
    for (int o = 0; o < 8; o++) { acc[o][0] = 0.f; acc[o][1] = 0.f; }

    const float* rb = rep + (b*CH)*HWN + px0;
    #pragma unroll 4
    for (int c = 0; c < CH; c++) {
        float2 px = *(const float2*)(rb + c*HWN);
        float4 w0 = *(const float4*)(&wt[c*32 + og*8]);
        float4 w1 = *(const float4*)(&wt[c*32 + og*8 + 4]);
        float wv[8] = {w0.x, w0.y, w0.z, w0.w, w1.x, w1.y, w1.z, w1.w};
        #pragma unroll
        for (int o = 0; o < 8; o++) {
            acc[o][0] = fmaf(wv[o], px.x, acc[o][0]);
            acc[o][1] = fmaf(wv[o], px.y, acc[o][1]);
        }
    }

    const float scale = 0.51006972f;    // log2(e) / sqrt(8): softmax via ex2
    const int head = (b*GG + g)*NHN + og;
    float bb[8];
    #pragma unroll
    for (int o = 0; o < 8; o++) bb[o] = bs[og*8 + o];
    #pragma unroll
    for (int p = 0; p < 2; p++) {
        int hw = px0 + p;
        g_q[(head*HWN + hw)*2    ] = make_float4((acc[0][p]+bb[0])*scale, (acc[1][p]+bb[1])*scale,
                                                 (acc[2][p]+bb[2])*scale, (acc[3][p]+bb[3])*scale);
        g_q[(head*HWN + hw)*2 + 1] = make_float4((acc[4][p]+bb[4])*scale, (acc[5][p]+bb[5])*scale,
                                                 (acc[6][p]+bb[6])*scale, (acc[7][p]+bb[7])*scale);
    }
}

// =============================================================================
// Fused main kernel: attention (576 blocks, dispatched FIRST) + conv_x (256)
// + conv_rep (128), all independent, 192 threads each. Conv blocks backfill
// SMs while attention drains -> convs hide under attention's runtime.
// =============================================================================

// ---- attn body: 3 queries/thread, ex2 softmax, no max (round-6 measured) ----
__device__ __forceinline__ void attn_body(int head, int kc, int tid)
{
    const int q0 = tid, q1 = tid + 192, q2 = tid + 384;

    const float4* Qp = g_q + head*HWN*2;
    float4 qA0 = __ldg(Qp + q0*2), qB0 = __ldg(Qp + q0*2 + 1);
    float4 qA1 = __ldg(Qp + q1*2), qB1 = __ldg(Qp + q1*2 + 1);
    float4 qA2 = __ldg(Qp + q2*2), qB2 = __ldg(Qp + q2*2 + 1);

    const float4* Kp = g_K + (head*TKEYS + kc*KPC)*2;
    const float4* Vp = g_V + (head*TKEYS + kc*KPC)*2;

    float l0 = 0.f, l1 = 0.f, l2 = 0.f;
    float a0[8], a1[8], a2[8];
    #pragma unroll
    for (int d = 0; d < 8; d++) { a0[d]=0.f; a1[d]=0.f; a2[d]=0.f; }

    #pragma unroll 2
    for (int j = 0; j < KPC; j++) {
        float4 ka = __ldg(Kp + j*2);
        float4 kb = __ldg(Kp + j*2 + 1);
        float s0 = qA0.x*ka.x + qA0.y*ka.y + qA0.z*ka.z + qA0.w*ka.w
                 + qB0.x*kb.x + qB0.y*kb.y + qB0.z*kb.z + qB0.w*kb.w;
        float s1 = qA1.x*ka.x + qA1.y*ka.y + qA1.z*ka.z + qA1.w*ka.w
                 + qB1.x*kb.x + qB1.y*kb.y + qB1.z*kb.z + qB1.w*kb.w;
        float s2 = qA2.x*ka.x + qA2.y*ka.y + qA2.z*ka.z + qA2.w*ka.w
                 + qB2.x*kb.x + qB2.y*kb.y + qB2.z*kb.z + qB2.w*kb.w;
        float p0 = ex2f(s0);      // Q pre-scaled by log2e -> true exp
        float p1 = ex2f(s1);
        float p2 = ex2f(s2);
        l0 += p0; l1 += p1; l2 += p2;
        float4 va = __ldg(Vp + j*2);
        float4 vb = __ldg(Vp + j*2 + 1);
        a0[0]=fmaf(p0,va.x,a0[0]); a0[1]=fmaf(p0,va.y,a0[1]); a0[2]=fmaf(p0,va.z,a0[2]); a0[3]=fmaf(p0,va.w,a0[3]);
        a0[4]=fmaf(p0,vb.x,a0[4]); a0[5]=fmaf(p0,vb.y,a0[5]); a0[6]=fmaf(p0,vb.z,a0[6]); a0[7]=fmaf(p0,vb.w,a0[7]);
        a1[0]=fmaf(p1,va.x,a1[0]); a1[1]=fmaf(p1,va.y,a1[1]); a1[2]=fmaf(p1,va.z,a1[2]); a1[3]=fmaf(p1,va.w,a1[3]);
        a1[4]=fmaf(p1,vb.x,a1[4]); a1[5]=fmaf(p1,vb.y,a1[5]); a1[6]=fmaf(p1,vb.z,a1[6]); a1[7]=fmaf(p1,vb.w,a1[7]);
        a2[0]=fmaf(p2,va.x,a2[0]); a2[1]=fmaf(p2,va.y,a2[1]); a2[2]=fmaf(p2,va.z,a2[2]); a2[3]=fmaf(p2,va.w,a2[3]);
        a2[4]=fmaf(p2,vb.x,a2[4]); a2[5]=fmaf(p2,vb.y,a2[5]); a2[6]=fmaf(p2,vb.z,a2[6]); a2[7]=fmaf(p2,vb.w,a2[7]);
    }

    const int base = (kc*HEADS + head)*HWN;
    g_L[base + q0] = l0;
    g_L[base + q1] = l1;
    g_L[base + q2] = l2;
    g_A[(base + q0)*2    ] = make_float4(a0[0], a0[1], a0[2], a0[3]);
    g_A[(base + q0)*2 + 1] = make_float4(a0[4], a0[5], a0[6], a0[7]);
    g_A[(base + q1)*2    ] = make_float4(a1[0], a1[1], a1[2], a1[3]);
    g_A[(base + q1)*2 + 1] = make_float4(a1[4], a1[5], a1[6], a1[7]);
    g_A[(base + q2)*2    ] = make_float4(a2[0], a2[1], a2[2], a2[3]);
    g_A[(base + q2)*2 + 1] = make_float4(a2[4], a2[5], a2[6], a2[7]);
}

// ---- conv body: 4 gates, 3 pixels per thread (192 thr x 3 = 576 px) ---------
template<int IC, int OC, int WHICH>
__device__ __forceinline__
void conv_body(const float* __restrict__ in,   // [B][IC][24][24]
               const float* __restrict__ w,    // [G][OC][IC][3][3]
               const float* __restrict__ bias, // [G][OC]
               int idx, int tid, float* ws)
{
    const int b  = idx & 3;
    const int oc = idx >> 2;

    for (int i = tid; i < GG*IC*9; i += 192) {
        int g = i / (IC*9);
        int r = i - g*(IC*9);
        ws[i] = w[(g*OC + oc)*IC*9 + r];
    }
    __syncthreads();

    const int p0 = tid, p1 = tid + 192, p2 = tid + 384;
    const int y0 = p0 / WW, x0 = p0 % WW;
    const int y1 = p1 / WW, x1 = p1 % WW;
    const int y2 = p2 / WW, x2 = p2 % WW;

    float acc0[GG], acc1[GG], acc2[GG];
    #pragma unroll
    for (int g = 0; g < GG; g++) {
        float bv = __ldg(bias + g*OC + oc);
        acc0[g] = bv; acc1[g] = bv; acc2[g] = bv;
    }

    for (int ic = 0; ic < IC; ic++) {
        const float* ip = in + (b*IC + ic)*HWN;
        float v0[9], v1[9], v2[9];
        #pragma unroll
        for (int ky = 0; ky < 3; ky++) {
            #pragma unroll
            for (int kx = 0; kx < 3; kx++) {
                int iy = y0 + ky - 1, ix = x0 + kx - 1;
                v0[ky*3+kx] = (iy >= 0 && iy < HH && ix >= 0 && ix < WW)
                              ? __ldg(ip + iy*WW + ix) : 0.f;
                int jy = y1 + ky - 1, jx = x1 + kx - 1;
                v1[ky*3+kx] = (jy >= 0 && jy < HH && jx >= 0 && jx < WW)
                              ? __ldg(ip + jy*WW + jx) : 0.f;
                int zy = y2 + ky - 1, zx = x2 + kx - 1;
                v2[ky*3+kx] = (zy >= 0 && zy < HH && zx >= 0 && zx < WW)
                              ? __ldg(ip + zy*WW + zx) : 0.f;
            }
        }
        #pragma unroll
        for (int g = 0; g < GG; g++) {
            const float* wp = &ws[(g*IC + ic)*9];
            #pragma unroll
            for (int kk = 0; kk < 9; kk++) {
                float wv = wp[kk];
                acc0[g] = fmaf(v0[kk], wv, acc0[g]);
                acc1[g] = fmaf(v1[kk], wv, acc1[g]);
                acc2[g] = fmaf(v2[kk], wv, acc2[g]);
            }
        }
    }
    float* out = (WHICH == 0) ? g_xg : g_co;
    #pragma unroll
    for (int g = 0; g < GG; g++) {
        out[((b*GG + g)*OC + oc)*HWN + p0] = acc0[g];
        out[((b*GG + g)*OC + oc)*HWN + p1] = acc1[g];
        out[((b*GG + g)*OC + oc)*HWN + p2] = acc2[g];
    }
}

__global__ __launch_bounds__(192)
void main_fused_kernel(const float* __restrict__ inputs,
                       const float* __restrict__ rep,
                       const float* __restrict__ Wx_w, const float* __restrict__ Wx_b,
                       const float* __restrict__ conv_w, const float* __restrict__ conv_b)
{
    __shared__ float ws[GG*CH*9];     // 2304 floats (worst case: conv_rep IC=64)
    const int bid = blockIdx.x;
    const int tid = threadIdx.x;
    if (bid < HEADS*KC) {
        // attention first: fills SMs, convs backfill behind it
        attn_body(bid % HEADS, bid / HEADS, tid);
    } else if (bid < HEADS*KC + CH*BB) {
        conv_body<CIN, CH, 0>(inputs, Wx_w, Wx_b, bid - HEADS*KC, tid, ws);
    } else {
        conv_body<CH, CH-DV, 1>(rep, conv_w, conv_b, bid - (HEADS*KC + CH*BB), tid, ws);
    }
}

// ---------------- combine partials + output projection ----------------------
__global__ __launch_bounds__(192)
void proj_kernel(const float* __restrict__ pw,  // [G][DV][DV]
                 const float* __restrict__ pb)  // [G][DV]
{
    const int b = blockIdx.x, g = blockIdx.y, hwc = blockIdx.z;
    const int tid = threadIdx.x;
    const int hw = hwc*192 + tid;

    __shared__ float ws[DV*DV];
    for (int i = tid; i < DV*DV; i += 192) ws[i] = pw[g*DV*DV + i];
    __syncthreads();

    float av[DV];
    #pragma unroll
    for (int n = 0; n < NHN; n++) {
        int head = (b*GG + g)*NHN + n;
        int qi = head*HWN + hw;
        float l = 0.f;
        float4 s0 = make_float4(0.f,0.f,0.f,0.f);
        float4 s1 = make_float4(0.f,0.f,0.f,0.f);
        #pragma unroll
        for (int kcc = 0; kcc < KC; kcc++) {
            int idx = kcc*HEADS*HWN + qi;
            l += g_L[idx];
            float4 t0 = g_A[idx*2], t1 = g_A[idx*2 + 1];
            s0.x += t0.x; s0.y += t0.y; s0.z += t0.z; s0.w += t0.w;
            s1.x += t1.x; s1.y += t1.y; s1.z += t1.z; s1.w += t1.w;
        }
        float inv = 1.f / l;
        av[n*8 + 0] = s0.x*inv; av[n*8 + 1] = s0.y*inv;
        av[n*8 + 2] = s0.z*inv; av[n*8 + 3] = s0.w*inv;
        av[n*8 + 4] = s1.x*inv; av[n*8 + 5] = s1.y*inv;
        av[n*8 + 6] = s1.z*inv; av[n*8 + 7] = s1.w*inv;
    }

    #pragma unroll 4
    for (int dout = 0; dout < DV; dout++) {
        float o = __ldg(pb + g*DV + dout);
        #pragma unroll
        for (int di = 0; di < DV; di++) o = fmaf(av[di], ws[dout*DV + di], o);
        g_attnp[((b*GG + g)*DV + dout)*HWN + hw] = o;
    }
}

// ---------------- LSTM gates ------------------------------------------------
__device__ __forceinline__ float sigmf(float x) { return 1.f / (1.f + __expf(-x)); }

__global__ __launch_bounds__(576)
void gates_kernel(const float* __restrict__ c_in,
                  const float* __restrict__ Wci,
                  const float* __restrict__ Wcf,
                  const float* __restrict__ Wco,
                  float* __restrict__ out)
{
    const int b  = blockIdx.x >> 6;
    const int ch = blockIdx.x & 63;
    const int hw = threadIdx.x;

    float pre[GG];
    #pragma unroll
    for (int g = 0; g < GG; g++) {
        float x = g_xg[((b*GG + g)*CH + ch)*HWN + hw];
        float y = (ch < 32) ? g_co[((b*GG + g)*(CH-DV) + ch)*HWN + hw]
                            : g_attnp[((b*GG + g)*DV + (ch - 32))*HWN + hw];
        pre[g] = x + y;
    }

    float c  = __ldg(c_in + (b*CH + ch)*HWN + hw);
    float ci = __ldg(Wci + ch*HWN + hw);
    float cf = __ldg(Wcf + ch*HWN + hw);
    float co = __ldg(Wco + ch*HWN + hw);

    float i_t = sigmf(pre[0] + c*ci);
    float f_t = sigmf(pre[1] + c*cf + 1.0f);
    float c_t = f_t*c + i_t*tanhf(pre[2]);
    float o_t = sigmf(pre[3] + c_t*co);
    float h_t = o_t*tanhf(c_t);

    const int idx = (b*CH + ch)*HWN + hw;
    out[idx] = h_t;
    out[BB*CH*HWN + idx] = c_t;
}

// ---------------- launcher ---------------------------------------------------
extern "C" void kernel_launch(void* const* d_in, const int* in_sizes, int n_in,
                              void* d_out, int out_size)
{
    const float* inputs  = (const float*)d_in[0];
    const float* rep     = (const float*)d_in[1];
    const float* c_in    = (const float*)d_in[2];
    const float* history = (const float*)d_in[3];
    const float* Wx_w    = (const float*)d_in[4];
    const float* Wx_b    = (const float*)d_in[5];
    const float* conv_w  = (const float*)d_in[6];
    const float* conv_b  = (const float*)d_in[7];
    const float* q_w     = (const float*)d_in[8];
    const float* q_b     = (const float*)d_in[9];
    const float* kv_w    = (const float*)d_in[10];
    const float* kv_b    = (const float*)d_in[11];
    const float* proj_w  = (const float*)d_in[12];
    const float* proj_b  = (const float*)d_in[13];
    const float* Wci     = (const float*)d_in[14];
    const float* Wcf     = (const float*)d_in[15];
    const float* Wco     = (const float*)d_in[16];
    float* out = (float*)d_out;
    (void)in_sizes; (void)n_in; (void)out_size;

    // Q and KV projections (attention inputs)
    q_tiled_kernel<<<dim3(BB*GG, 4), 288>>>(rep, q_w, q_b);
    kv_tiled_kernel<<<dim3(TT*4, BB*GG, 2), 288>>>(history, kv_w, kv_b);
    // fused: attention (576 blocks first) + conv_x (256) + conv_rep (128)
    main_fused_kernel<<<HEADS*KC + CH*BB + (CH-DV)*BB, 192>>>(
        inputs, rep, Wx_w, Wx_b, conv_w, conv_b);
    // combine + projection
    proj_kernel<<<dim3(BB, GG, 3), 192>>>(proj_w, proj_b);
    // LSTM gates -> h_t, c_t
    gates_kernel<<<BB*CH, HWN>>>(c_in, Wci, Wcf, Wco, out);
}

// round 12
// speedup vs baseline: 1.2617x; 1.2617x over previous
#include <cuda_runtime.h>
#include <math.h>

// Problem constants
#define BB   4
#define CIN  32
#define CH   64
#define HH   24
#define WW   24
#define HWN  576          // 24*24
#define TT   5
#define DK   32
#define DV   32
#define NHN  4
#define GG   4
#define HEADS 64          // B*G*NH
#define TKEYS 2880        // T*HW
#define KC    9           // key chunks
#define KPC   320         // keys per chunk
#define ATTN_THREADS 192  // 3 queries per thread

// ---------------- scratch (device globals; no allocation allowed) -------------
__device__ float  g_xg[BB*GG*CH*HWN];        // conv on inputs, 4 gates x 64 ch
__device__ float  g_co[BB*GG*(CH-DV)*HWN];   // conv on rep, 4 gates x 32 ch
__device__ float4 g_q[HEADS*HWN*2];          // Q [head][q][8] (scaled by log2e/sqrt8)
__device__ float4 g_K[HEADS*TKEYS*2];        // K [head][j][8]
__device__ float4 g_V[HEADS*TKEYS*2];        // V [head][j][8]
__device__ float  g_L[KC*HEADS*HWN];         // partial exp-sums
__device__ float4 g_A[KC*HEADS*HWN*2];       // partial weighted V sums
__device__ float  g_attnp[BB*GG*DV*HWN];     // projected attention

__device__ __forceinline__ float ex2f(float x) {
    float r; asm("ex2.approx.ftz.f32 %0,%1;" : "=f"(r) : "f"(x)); return r;
}

// ---------------- conv: 4 gates per thread, 2 pixels per thread (round-6) ----
template<int IC, int OC, int WHICH>
__global__ __launch_bounds__(288)
void conv4g_kernel(const float* __restrict__ in,   // [B][IC][24][24]
                   const float* __restrict__ w,    // [G][OC][IC][3][3]
                   const float* __restrict__ bias) // [G][OC]
{
    const int oc = blockIdx.x;
    const int b  = blockIdx.y;
    const int tid = threadIdx.x;

    __shared__ float ws[GG*IC*9];
    for (int i = tid; i < GG*IC*9; i += 288) {
        int g = i / (IC*9);
        int r = i - g*(IC*9);
        ws[i] = w[(g*OC + oc)*IC*9 + r];
    }
    __syncthreads();

    const int p0 = tid, p1 = tid + 288;
    const int y0 = p0 / WW, x0 = p0 % WW;
    const int y1 = p1 / WW, x1 = p1 % WW;

    float acc0[GG], acc1[GG];
    #pragma unroll
    for (int g = 0; g < GG; g++) {
        float bv = __ldg(bias + g*OC + oc);
        acc0[g] = bv; acc1[g] = bv;
    }

    for (int ic = 0; ic < IC; ic++) {
        const float* ip = in + (b*IC + ic)*HWN;
        float v0[9], v1[9];
        #pragma unroll
        for (int ky = 0; ky < 3; ky++) {
            #pragma unroll
            for (int kx = 0; kx < 3; kx++) {
                int iy = y0 + ky - 1, ix = x0 + kx - 1;
                v0[ky*3+kx] = (iy >= 0 && iy < HH && ix >= 0 && ix < WW)
                              ? __ldg(ip + iy*WW + ix) : 0.f;
                int jy = y1 + ky - 1, jx = x1 + kx - 1;
                v1[ky*3+kx] = (jy >= 0 && jy < HH && jx >= 0 && jx < WW)
                              ? __ldg(ip + jy*WW + jx) : 0.f;
            }
        }
        #pragma unroll
        for (int g = 0; g < GG; g++) {
            const float* wp = &ws[(g*IC + ic)*9];
            #pragma unroll
            for (int kk = 0; kk < 9; kk++) {
                float wv = wp[kk];
                acc0[g] = fmaf(v0[kk], wv, acc0[g]);
                acc1[g] = fmaf(v1[kk], wv, acc1[g]);
            }
        }
    }
    float* out = (WHICH == 0) ? g_xg : g_co;
    #pragma unroll
    for (int g = 0; g < GG; g++) {
        out[((b*GG + g)*OC + oc)*HWN + p0] = acc0[g];
        out[((b*GG + g)*OC + oc)*HWN + p1] = acc1[g];
    }
}

// ---------------- KV projection, register-tiled, 640 blocks -------------------
__global__ __launch_bounds__(288)
void kv_tiled_kernel(const float* __restrict__ hist, // [B][T][CH][HW]
                     const float* __restrict__ kvw,  // [G][DK+DV][CH]
                     const float* __restrict__ kvb)  // [G][DK+DV]
{
    const int t    = blockIdx.x >> 2;
    const int pc   = blockIdx.x & 3;
    const int b    = blockIdx.y >> 2;
    const int g    = blockIdx.y & 3;
    const int half = blockIdx.z;
    const int tid  = threadIdx.x;
    const int og   = tid & 3;
    const int pg   = tid >> 2;          // 0..71

    __shared__ float wt[CH*32];         // [c][e] transposed
    __shared__ float bs[32];
    for (int i = tid; i < CH*32; i += 288) {
        int e = i & 31, c = i >> 5;
        wt[c*32 + e] = kvw[(g*(DK+DV) + half*32 + e)*CH + c];
    }
    if (tid < 32) bs[tid] = kvb[g*(DK+DV) + half*32 + tid];
    __syncthreads();

    float acc[8][2];
    #pragma unroll
    for (int o = 0; o < 8; o++) { acc[o][0] = 0.f; acc[o][1] = 0.f; }

    const int pxbase = pc*144 + pg*2;
    const float* hb = hist + ((b*TT + t)*CH)*HWN + pxbase;
    #pragma unroll 4
    for (int c = 0; c < CH; c++) {
        float2 px = *(const float2*)(hb + c*HWN);
        float4 w0 = *(const float4*)(&wt[c*32 + og*8]);
        float4 w1 = *(const float4*)(&wt[c*32 + og*8 + 4]);
        float wv[8] = {w0.x, w0.y, w0.z, w0.w, w1.x, w1.y, w1.z, w1.w};
        #pragma unroll
        for (int o = 0; o < 8; o++) {
            acc[o][0] = fmaf(wv[o], px.x, acc[o][0]);
            acc[o][1] = fmaf(wv[o], px.y, acc[o][1]);
        }
    }

    const int head = (b*GG + g)*NHN + og;
    float4* dst = (half == 0) ? g_K : g_V;
    float bb[8];
    #pragma unroll
    for (int o = 0; o < 8; o++) bb[o] = bs[og*8 + o];
    #pragma unroll
    for (int p = 0; p < 2; p++) {
        int j = t*HWN + pxbase + p;
        dst[(head*TKEYS + j)*2    ] = make_float4(acc[0][p]+bb[0], acc[1][p]+bb[1],
                                                  acc[2][p]+bb[2], acc[3][p]+bb[3]);
        dst[(head*TKEYS + j)*2 + 1] = make_float4(acc[4][p]+bb[4], acc[5][p]+bb[5],
                                                  acc[6][p]+bb[6], acc[7][p]+bb[7]);
    }
}

// ---------------- Q projection, 288-thread blocks, scale folds log2e ---------
__global__ __launch_bounds__(288)
void q_tiled_kernel(const float* __restrict__ rep,  // [B][CH][HW]
                    const float* __restrict__ qw,   // [G][DK][CH]
                    const float* __restrict__ qb)   // [G][DK]
{
    const int b     = blockIdx.x >> 2;
    const int g     = blockIdx.x & 3;
    const int chunk = blockIdx.y;       // 4 chunks of 144 px
    const int tid   = threadIdx.x;
    const int og    = tid & 3;
    const int pg    = tid >> 2;         // 0..71
    const int px0   = chunk*144 + pg*2;

    __shared__ float wt[CH*32];
    __shared__ float bs[32];
    for (int i = tid; i < CH*32; i += 288) {
        int e = i & 31, c = i >> 5;
        wt[c*32 + e] = qw[(g*DK + e)*CH + c];
    }
    if (tid < 32) bs[tid] = qb[g*DK + tid];
    __syncthreads();

    float acc[8][2];
    #pragma unroll
    for (int o = 0; o < 8; o++) { acc[o][0] = 0.f; acc[o][1] = 0.f; }

    const float* rb = rep + (b*CH)*HWN + px0;
    #pragma unroll 4
    for (int c = 0; c < CH; c++) {
        float2 px = *(const float2*)(rb + c*HWN);
        float4 w0 = *(const float4*)(&wt[c*32 + og*8]);
        float4 w1 = *(const float4*)(&wt[c*32 + og*8 + 4]);
        float wv[8] = {w0.x, w0.y, w0.z, w0.w, w1.x, w1.y, w1.z, w1.w};
        #pragma unroll
        for (int o = 0; o < 8; o++) {
            acc[o][0] = fmaf(wv[o], px.x, acc[o][0]);
            acc[o][1] = fmaf(wv[o], px.y, acc[o][1]);
        }
    }

    const float scale = 0.51006972f;    // log2(e) / sqrt(8): softmax via ex2
    const int head = (b*GG + g)*NHN + og;
    float bb[8];
    #pragma unroll
    for (int o = 0; o < 8; o++) bb[o] = bs[og*8 + o];
    #pragma unroll
    for (int p = 0; p < 2; p++) {
        int hw = px0 + p;
        g_q[(head*HWN + hw)*2    ] = make_float4((acc[0][p]+bb[0])*scale, (acc[1][p]+bb[1])*scale,
                                                 (acc[2][p]+bb[2])*scale, (acc[3][p]+bb[3])*scale);
        g_q[(head*HWN + hw)*2 + 1] = make_float4((acc[4][p]+bb[4])*scale, (acc[5][p]+bb[5])*scale,
                                                 (acc[6][p]+bb[6])*scale, (acc[7][p]+bb[7])*scale);
    }
}

// ---------------- attention: 3 queries/thread, ex2 softmax, no max (round-6) --
__global__ __launch_bounds__(ATTN_THREADS)
void attn_kernel()
{
    const int head = blockIdx.x;       // 0..63
    const int kc   = blockIdx.y;       // 0..8
    const int tid  = threadIdx.x;

    const int q0 = tid, q1 = tid + 192, q2 = tid + 384;

    const float4* Qp = g_q + head*HWN*2;
    float4 qA0 = __ldg(Qp + q0*2), qB0 = __ldg(Qp + q0*2 + 1);
    float4 qA1 = __ldg(Qp + q1*2), qB1 = __ldg(Qp + q1*2 + 1);
    float4 qA2 = __ldg(Qp + q2*2), qB2 = __ldg(Qp + q2*2 + 1);

    const float4* Kp = g_K + (head*TKEYS + kc*KPC)*2;
    const float4* Vp = g_V + (head*TKEYS + kc*KPC)*2;

    float l0 = 0.f, l1 = 0.f, l2 = 0.f;
    float a0[8], a1[8], a2[8];
    #pragma unroll
    for (int d = 0; d < 8; d++) { a0[d]=0.f; a1[d]=0.f; a2[d]=0.f; }

    #pragma unroll 2
    for (int j = 0; j < KPC; j++) {
        float4 ka = __ldg(Kp + j*2);
        float4 kb = __ldg(Kp + j*2 + 1);
        float s0 = qA0.x*ka.x + qA0.y*ka.y + qA0.z*ka.z + qA0.w*ka.w
                 + qB0.x*kb.x + qB0.y*kb.y + qB0.z*kb.z + qB0.w*kb.w;
        float s1 = qA1.x*ka.x + qA1.y*ka.y + qA1.z*ka.z + qA1.w*ka.w
                 + qB1.x*kb.x + qB1.y*kb.y + qB1.z*kb.z + qB1.w*kb.w;
        float s2 = qA2.x*ka.x + qA2.y*ka.y + qA2.z*ka.z + qA2.w*ka.w
                 + qB2.x*kb.x + qB2.y*kb.y + qB2.z*kb.z + qB2.w*kb.w;
        float p0 = ex2f(s0);      // Q pre-scaled by log2e -> true exp
        float p1 = ex2f(s1);
        float p2 = ex2f(s2);
        l0 += p0; l1 += p1; l2 += p2;
        float4 va = __ldg(Vp + j*2);
        float4 vb = __ldg(Vp + j*2 + 1);
        a0[0]=fmaf(p0,va.x,a0[0]); a0[1]=fmaf(p0,va.y,a0[1]); a0[2]=fmaf(p0,va.z,a0[2]); a0[3]=fmaf(p0,va.w,a0[3]);
        a0[4]=fmaf(p0,vb.x,a0[4]); a0[5]=fmaf(p0,vb.y,a0[5]); a0[6]=fmaf(p0,vb.z,a0[6]); a0[7]=fmaf(p0,vb.w,a0[7]);
        a1[0]=fmaf(p1,va.x,a1[0]); a1[1]=fmaf(p1,va.y,a1[1]); a1[2]=fmaf(p1,va.z,a1[2]); a1[3]=fmaf(p1,va.w,a1[3]);
        a1[4]=fmaf(p1,vb.x,a1[4]); a1[5]=fmaf(p1,vb.y,a1[5]); a1[6]=fmaf(p1,vb.z,a1[6]); a1[7]=fmaf(p1,vb.w,a1[7]);
        a2[0]=fmaf(p2,va.x,a2[0]); a2[1]=fmaf(p2,va.y,a2[1]); a2[2]=fmaf(p2,va.z,a2[2]); a2[3]=fmaf(p2,va.w,a2[3]);
        a2[4]=fmaf(p2,vb.x,a2[4]); a2[5]=fmaf(p2,vb.y,a2[5]); a2[6]=fmaf(p2,vb.z,a2[6]); a2[7]=fmaf(p2,vb.w,a2[7]);
    }

    const int base = (kc*HEADS + head)*HWN;
    g_L[base + q0] = l0;
    g_L[base + q1] = l1;
    g_L[base + q2] = l2;
    g_A[(base + q0)*2    ] = make_float4(a0[0], a0[1], a0[2], a0[3]);
    g_A[(base + q0)*2 + 1] = make_float4(a0[4], a0[5], a0[6], a0[7]);
    g_A[(base + q1)*2    ] = make_float4(a1[0], a1[1], a1[2], a1[3]);
    g_A[(base + q1)*2 + 1] = make_float4(a1[4], a1[5], a1[6], a1[7]);
    g_A[(base + q2)*2    ] = make_float4(a2[0], a2[1], a2[2], a2[3]);
    g_A[(base + q2)*2 + 1] = make_float4(a2[4], a2[5], a2[6], a2[7]);
}

// ---------------- combine + projection, 4-way head-split ----------------------
// Thread = (pixel, head): tid = px*4 + n. Each thread combines ONE head's 9
// partials (1/4 the dependent-load chain of the old version), stages av in
// padded smem, then computes that head's 8 output rows. Grid 192 blocks.
__global__ __launch_bounds__(192)
void proj_kernel(const float* __restrict__ pw,  // [G][DV][DV]
                 const float* __restrict__ pb)  // [G][DV]
{
    const int b = blockIdx.x, g = blockIdx.y, hwc = blockIdx.z;  // z: 0..11
    const int tid = threadIdx.x;
    const int px  = tid >> 2;          // 0..47 local pixel
    const int n   = tid & 3;           // head slot
    const int hw  = hwc*48 + px;

    __shared__ float ws[DV*DV];        // [dout][di]
    __shared__ float sav[48][DV + 1];  // +1 pad: conflict-free column reads
    for (int i = tid; i < DV*DV; i += 192) ws[i] = pw[g*DV*DV + i];

    // combine head n's partials for pixel hw
    const int head = (b*GG + g)*NHN + n;
    const int qi = head*HWN + hw;
    float l = 0.f;
    float4 s0 = make_float4(0.f,0.f,0.f,0.f);
    float4 s1 = make_float4(0.f,0.f,0.f,0.f);
    #pragma unroll
    for (int kcc = 0; kcc < KC; kcc++) {
        int idx = kcc*HEADS*HWN + qi;
        l += g_L[idx];
        float4 t0 = g_A[idx*2], t1 = g_A[idx*2 + 1];
        s0.x += t0.x; s0.y += t0.y; s0.z += t0.z; s0.w += t0.w;
        s1.x += t1.x; s1.y += t1.y; s1.z += t1.z; s1.w += t1.w;
    }
    float inv = 1.f / l;
    sav[px][n*8 + 0] = s0.x*inv; sav[px][n*8 + 1] = s0.y*inv;
    sav[px][n*8 + 2] = s0.z*inv; sav[px][n*8 + 3] = s0.w*inv;
    sav[px][n*8 + 4] = s1.x*inv; sav[px][n*8 + 5] = s1.y*inv;
    sav[px][n*8 + 6] = s1.z*inv; sav[px][n*8 + 7] = s1.w*inv;
    __syncthreads();

    // this thread computes douts n*8 .. n*8+7 for pixel hw
    const float* avp = sav[px];
    #pragma unroll
    for (int dd = 0; dd < 8; dd++) {
        int dout = n*8 + dd;
        float o = __ldg(pb + g*DV + dout);
        const float* wrow = &ws[dout*DV];
        #pragma unroll
        for (int di = 0; di < DV; di++) o = fmaf(avp[di], wrow[di], o);
        g_attnp[((b*GG + g)*DV + dout)*HWN + hw] = o;
    }
}

// ---------------- LSTM gates ------------------------------------------------
__device__ __forceinline__ float sigmf(float x) { return 1.f / (1.f + __expf(-x)); }

__global__ __launch_bounds__(576)
void gates_kernel(const float* __restrict__ c_in,
                  const float* __restrict__ Wci,
                  const float* __restrict__ Wcf,
                  const float* __restrict__ Wco,
                  float* __restrict__ out)
{
    const int b  = blockIdx.x >> 6;
    const int ch = blockIdx.x & 63;
    const int hw = threadIdx.x;

    float pre[GG];
    #pragma unroll
    for (int g = 0; g < GG; g++) {
        float x = g_xg[((b*GG + g)*CH + ch)*HWN + hw];
        float y = (ch < 32) ? g_co[((b*GG + g)*(CH-DV) + ch)*HWN + hw]
                            : g_attnp[((b*GG + g)*DV + (ch - 32))*HWN + hw];
        pre[g] = x + y;
    }

    float c  = __ldg(c_in + (b*CH + ch)*HWN + hw);
    float ci = __ldg(Wci + ch*HWN + hw);
    float cf = __ldg(Wcf + ch*HWN + hw);
    float co = __ldg(Wco + ch*HWN + hw);

    float i_t = sigmf(pre[0] + c*ci);
    float f_t = sigmf(pre[1] + c*cf + 1.0f);
    float c_t = f_t*c + i_t*tanhf(pre[2]);
    float o_t = sigmf(pre[3] + c_t*co);
    float h_t = o_t*tanhf(c_t);

    const int idx = (b*CH + ch)*HWN + hw;
    out[idx] = h_t;
    out[BB*CH*HWN + idx] = c_t;
}

// ---------------- launcher ---------------------------------------------------
extern "C" void kernel_launch(void* const* d_in, const int* in_sizes, int n_in,
                              void* d_out, int out_size)
{
    const float* inputs  = (const float*)d_in[0];
    const float* rep     = (const float*)d_in[1];
    const float* c_in    = (const float*)d_in[2];
    const float* history = (const float*)d_in[3];
    const float* Wx_w    = (const float*)d_in[4];
    const float* Wx_b    = (const float*)d_in[5];
    const float* conv_w  = (const float*)d_in[6];
    const float* conv_b  = (const float*)d_in[7];
    const float* q_w     = (const float*)d_in[8];
    const float* q_b     = (const float*)d_in[9];
    const float* kv_w    = (const float*)d_in[10];
    const float* kv_b    = (const float*)d_in[11];
    const float* proj_w  = (const float*)d_in[12];
    const float* proj_b  = (const float*)d_in[13];
    const float* Wci     = (const float*)d_in[14];
    const float* Wcf     = (const float*)d_in[15];
    const float* Wco     = (const float*)d_in[16];
    float* out = (float*)d_out;
    (void)in_sizes; (void)n_in; (void)out_size;

    // projections first (attention is the critical path)
    q_tiled_kernel<<<dim3(BB*GG, 4), 288>>>(rep, q_w, q_b);
    kv_tiled_kernel<<<dim3(TT*4, BB*GG, 2), 288>>>(history, kv_w, kv_b);
    // attention (partials over 9 key chunks)
    attn_kernel<<<dim3(HEADS, KC), ATTN_THREADS>>>();
    // convs (round-6 proven form)
    conv4g_kernel<CIN, CH, 0><<<dim3(CH, BB), 288>>>(inputs, Wx_w, Wx_b);
    conv4g_kernel<CH, CH-DV, 1><<<dim3(CH-DV, BB), 288>>>(rep, conv_w, conv_b);
    // combine + projection (4-way head split, 192 blocks)
    proj_kernel<<<dim3(BB, GG, 12), 192>>>(proj_w, proj_b);
    // LSTM gates -> h_t, c_t
    gates_kernel<<<BB*CH, HWN>>>(c_in, Wci, Wcf, Wco, out);
}

// round 13
// speedup vs baseline: 1.4362x; 1.1383x over previous
#include <cuda_runtime.h>
#include <cuda_fp16.h>
#include <math.h>

// Problem constants
#define BB   4
#define CIN  32
#define CH   64
#define HH   24
#define WW   24
#define HWN  576          // 24*24
#define TT   5
#define DK   32
#define DV   32
#define NHN  4
#define GG   4
#define HEADS 64          // B*G*NH
#define TKEYS 2880        // T*HW
#define NPAIRS 1440       // key pairs per head
#define KC    9           // key chunks
#define KPC   320         // keys per chunk
#define PPC   160         // key-pairs per chunk
#define ATTN_THREADS 192  // 3 queries per thread

// ---------------- scratch (device globals; no allocation allowed) -------------
__device__ float   g_xg[BB*GG*CH*HWN];       // conv on inputs, 4 gates x 64 ch
__device__ float   g_co[BB*GG*(CH-DV)*HWN];  // conv on rep, 4 gates x 32 ch
__device__ __half  g_qh[HEADS*HWN*8];        // Q [head][q][8] half (scaled log2e/sqrt8)
__device__ __half2 g_Kh[HEADS*NPAIRS*8];     // K [head][pair][dim] = (k_j0, k_j1)
__device__ __half2 g_Vh[HEADS*NPAIRS*8];     // V same layout
__device__ float   g_L[KC*HEADS*HWN];        // partial exp-sums (fp32)
__device__ float4  g_A[KC*HEADS*HWN*2];      // partial weighted V sums (fp32)
__device__ float   g_attnp[BB*GG*DV*HWN];    // projected attention

// ---------------- conv: 4 gates per thread, 2 pixels per thread (round-6) ----
template<int IC, int OC, int WHICH>
__global__ __launch_bounds__(288)
void conv4g_kernel(const float* __restrict__ in,   // [B][IC][24][24]
                   const float* __restrict__ w,    // [G][OC][IC][3][3]
                   const float* __restrict__ bias) // [G][OC]
{
    const int oc = blockIdx.x;
    const int b  = blockIdx.y;
    const int tid = threadIdx.x;

    __shared__ float ws[GG*IC*9];
    for (int i = tid; i < GG*IC*9; i += 288) {
        int g = i / (IC*9);
        int r = i - g*(IC*9);
        ws[i] = w[(g*OC + oc)*IC*9 + r];
    }
    __syncthreads();

    const int p0 = tid, p1 = tid + 288;
    const int y0 = p0 / WW, x0 = p0 % WW;
    const int y1 = p1 / WW, x1 = p1 % WW;

    float acc0[GG], acc1[GG];
    #pragma unroll
    for (int g = 0; g < GG; g++) {
        float bv = __ldg(bias + g*OC + oc);
        acc0[g] = bv; acc1[g] = bv;
    }

    for (int ic = 0; ic < IC; ic++) {
        const float* ip = in + (b*IC + ic)*HWN;
        float v0[9], v1[9];
        #pragma unroll
        for (int ky = 0; ky < 3; ky++) {
            #pragma unroll
            for (int kx = 0; kx < 3; kx++) {
                int iy = y0 + ky - 1, ix = x0 + kx - 1;
                v0[ky*3+kx] = (iy >= 0 && iy < HH && ix >= 0 && ix < WW)
                              ? __ldg(ip + iy*WW + ix) : 0.f;
                int jy = y1 + ky - 1, jx = x1 + kx - 1;
                v1[ky*3+kx] = (jy >= 0 && jy < HH && jx >= 0 && jx < WW)
                              ? __ldg(ip + jy*WW + jx) : 0.f;
            }
        }
        #pragma unroll
        for (int g = 0; g < GG; g++) {
            const float* wp = &ws[(g*IC + ic)*9];
            #pragma unroll
            for (int kk = 0; kk < 9; kk++) {
                float wv = wp[kk];
                acc0[g] = fmaf(v0[kk], wv, acc0[g]);
                acc1[g] = fmaf(v1[kk], wv, acc1[g]);
            }
        }
    }
    float* out = (WHICH == 0) ? g_xg : g_co;
    #pragma unroll
    for (int g = 0; g < GG; g++) {
        out[((b*GG + g)*OC + oc)*HWN + p0] = acc0[g];
        out[((b*GG + g)*OC + oc)*HWN + p1] = acc1[g];
    }
}

// ---------------- KV projection -> half2 key-pair layout ----------------------
// Same micro-GEMM as round 12; epilogue converts the 2 adjacent pixels (= one
// key pair) to half2 per dim.
__global__ __launch_bounds__(288)
void kv_tiled_kernel(const float* __restrict__ hist, // [B][T][CH][HW]
                     const float* __restrict__ kvw,  // [G][DK+DV][CH]
                     const float* __restrict__ kvb)  // [G][DK+DV]
{
    const int t    = blockIdx.x >> 2;
    const int pc   = blockIdx.x & 3;
    const int b    = blockIdx.y >> 2;
    const int g    = blockIdx.y & 3;
    const int half = blockIdx.z;
    const int tid  = threadIdx.x;
    const int og   = tid & 3;
    const int pg   = tid >> 2;          // 0..71

    __shared__ float wt[CH*32];         // [c][e] transposed
    __shared__ float bs[32];
    for (int i = tid; i < CH*32; i += 288) {
        int e = i & 31, c = i >> 5;
        wt[c*32 + e] = kvw[(g*(DK+DV) + half*32 + e)*CH + c];
    }
    if (tid < 32) bs[tid] = kvb[g*(DK+DV) + half*32 + tid];
    __syncthreads();

    float acc[8][2];
    #pragma unroll
    for (int o = 0; o < 8; o++) { acc[o][0] = 0.f; acc[o][1] = 0.f; }

    const int pxbase = pc*144 + pg*2;
    const float* hb = hist + ((b*TT + t)*CH)*HWN + pxbase;
    #pragma unroll 4
    for (int c = 0; c < CH; c++) {
        float2 px = *(const float2*)(hb + c*HWN);
        float4 w0 = *(const float4*)(&wt[c*32 + og*8]);
        float4 w1 = *(const float4*)(&wt[c*32 + og*8 + 4]);
        float wv[8] = {w0.x, w0.y, w0.z, w0.w, w1.x, w1.y, w1.z, w1.w};
        #pragma unroll
        for (int o = 0; o < 8; o++) {
            acc[o][0] = fmaf(wv[o], px.x, acc[o][0]);
            acc[o][1] = fmaf(wv[o], px.y, acc[o][1]);
        }
    }

    const int head = (b*GG + g)*NHN + og;
    const int jp = (t*HWN + pxbase) >> 1;   // key-pair index (pxbase is even)
    __half2* dst = ((half == 0) ? g_Kh : g_Vh) + (head*NPAIRS + jp)*8;
    #pragma unroll
    for (int o = 0; o < 8; o++) {
        float bb = bs[og*8 + o];
        dst[o] = __floats2half2_rn(acc[o][0] + bb, acc[o][1] + bb);
    }
}

// ---------------- Q projection -> half, scale folds log2e/sqrt8 ---------------
__global__ __launch_bounds__(288)
void q_tiled_kernel(const float* __restrict__ rep,  // [B][CH][HW]
                    const float* __restrict__ qw,   // [G][DK][CH]
                    const float* __restrict__ qb)   // [G][DK]
{
    const int b     = blockIdx.x >> 2;
    const int g     = blockIdx.x & 3;
    const int chunk = blockIdx.y;       // 4 chunks of 144 px
    const int tid   = threadIdx.x;
    const int og    = tid & 3;
    const int pg    = tid >> 2;         // 0..71
    const int px0   = chunk*144 + pg*2;

    __shared__ float wt[CH*32];
    __shared__ float bs[32];
    for (int i = tid; i < CH*32; i += 288) {
        int e = i & 31, c = i >> 5;
        wt[c*32 + e] = qw[(g*DK + e)*CH + c];
    }
    if (tid < 32) bs[tid] = qb[g*DK + tid];
    __syncthreads();

    float acc[8][2];
    #pragma unroll
    for (int o = 0; o < 8; o++) { acc[o][0] = 0.f; acc[o][1] = 0.f; }

    const float* rb = rep + (b*CH)*HWN + px0;
    #pragma unroll 4
    for (int c = 0; c < CH; c++) {
        float2 px = *(const float2*)(rb + c*HWN);
        float4 w0 = *(const float4*)(&wt[c*32 + og*8]);
        float4 w1 = *(const float4*)(&wt[c*32 + og*8 + 4]);
        float wv[8] = {w0.x, w0.y, w0.z, w0.w, w1.x, w1.y, w1.z, w1.w};
        #pragma unroll
        for (int o = 0; o < 8; o++) {
            acc[o][0] = fmaf(wv[o], px.x, acc[o][0]);
            acc[o][1] = fmaf(wv[o], px.y, acc[o][1]);
        }
    }

    const float scale = 0.51006972f;    // log2(e)/sqrt(8): softmax via exp2
    const int head = (b*GG + g)*NHN + og;
    float bb[8];
    #pragma unroll
    for (int o = 0; o < 8; o++) bb[o] = bs[og*8 + o];
    __half* dst = g_qh + (head*HWN + px0)*8;
    #pragma unroll
    for (int p = 0; p < 2; p++)
        #pragma unroll
        for (int o = 0; o < 8; o++)
            dst[p*8 + o] = __float2half((acc[o][p] + bb[o])*scale);
}

// ---------------- attention: half2 key-pairs, HFMA2, h2exp2 -------------------
// 3 queries/thread, 192 threads. Per key-pair: 24 HFMA2 (s) + 3 h2exp2
// + 3 HADD2 (l) + 24 HFMA2 (AV) + 4 LDG.128 -> 2x fma-pipe throughput vs fp32.
__global__ __launch_bounds__(ATTN_THREADS)
void attn_kernel()
{
    const int head = blockIdx.x;       // 0..63
    const int kc   = blockIdx.y;       // 0..8
    const int tid  = threadIdx.x;

    const int q0 = tid, q1 = tid + 192, q2 = tid + 384;

    // load 3 queries, broadcast each dim into half2
    __half2 Q0[8], Q1[8], Q2[8];
    {
        uint4 v0 = __ldg((const uint4*)(g_qh + (head*HWN + q0)*8));
        uint4 v1 = __ldg((const uint4*)(g_qh + (head*HWN + q1)*8));
        uint4 v2 = __ldg((const uint4*)(g_qh + (head*HWN + q2)*8));
        const __half* h0 = (const __half*)&v0;
        const __half* h1 = (const __half*)&v1;
        const __half* h2 = (const __half*)&v2;
        #pragma unroll
        for (int d = 0; d < 8; d++) {
            Q0[d] = __half2half2(h0[d]);
            Q1[d] = __half2half2(h1[d]);
            Q2[d] = __half2half2(h2[d]);
        }
    }

    const uint4* Kp = (const uint4*)(g_Kh + (head*NPAIRS + kc*PPC)*8);
    const uint4* Vp = (const uint4*)(g_Vh + (head*NPAIRS + kc*PPC)*8);

    __half2 l20 = __float2half2_rn(0.f);
    __half2 l21 = l20, l22 = l20;
    __half2 a0[8], a1[8], a2[8];
    #pragma unroll
    for (int d = 0; d < 8; d++) { a0[d] = l20; a1[d] = l20; a2[d] = l20; }

    #pragma unroll 2
    for (int jp = 0; jp < PPC; jp++) {
        uint4 ka = __ldg(Kp + jp*2);
        uint4 kb = __ldg(Kp + jp*2 + 1);
        const __half2* k0 = (const __half2*)&ka;   // dims 0..3
        const __half2* k1 = (const __half2*)&kb;   // dims 4..7

        __half2 s0 = __hmul2(Q0[0], k0[0]);
        __half2 s1 = __hmul2(Q1[0], k0[0]);
        __half2 s2 = __hmul2(Q2[0], k0[0]);
        #pragma unroll
        for (int d = 1; d < 4; d++) {
            s0 = __hfma2(Q0[d], k0[d], s0);
            s1 = __hfma2(Q1[d], k0[d], s1);
            s2 = __hfma2(Q2[d], k0[d], s2);
        }
        #pragma unroll
        for (int d = 0; d < 4; d++) {
            s0 = __hfma2(Q0[4+d], k1[d], s0);
            s1 = __hfma2(Q1[4+d], k1[d], s1);
            s2 = __hfma2(Q2[4+d], k1[d], s2);
        }

        __half2 p0 = h2exp2(s0);   // Q pre-scaled by log2e -> true exp
        __half2 p1 = h2exp2(s1);
        __half2 p2 = h2exp2(s2);
        l20 = __hadd2(l20, p0);
        l21 = __hadd2(l21, p1);
        l22 = __hadd2(l22, p2);

        uint4 va = __ldg(Vp + jp*2);
        uint4 vb = __ldg(Vp + jp*2 + 1);
        const __half2* v0 = (const __half2*)&va;
        const __half2* v1 = (const __half2*)&vb;
        #pragma unroll
        for (int d = 0; d < 4; d++) {
            a0[d]   = __hfma2(p0, v0[d], a0[d]);
            a1[d]   = __hfma2(p1, v0[d], a1[d]);
            a2[d]   = __hfma2(p2, v0[d], a2[d]);
            a0[4+d] = __hfma2(p0, v1[d], a0[4+d]);
            a1[4+d] = __hfma2(p1, v1[d], a1[4+d]);
            a2[4+d] = __hfma2(p2, v1[d], a2[4+d]);
        }
    }

    const int base = (kc*HEADS + head)*HWN;
    // epilogue: fold key-pair halves into fp32 partials (proj stays fp32)
    {
        float2 lf = __half22float2(l20);
        g_L[base + q0] = lf.x + lf.y;
        float r[8];
        #pragma unroll
        for (int d = 0; d < 8; d++) { float2 f = __half22float2(a0[d]); r[d] = f.x + f.y; }
        g_A[(base + q0)*2    ] = make_float4(r[0], r[1], r[2], r[3]);
        g_A[(base + q0)*2 + 1] = make_float4(r[4], r[5], r[6], r[7]);
    }
    {
        float2 lf = __half22float2(l21);
        g_L[base + q1] = lf.x + lf.y;
        float r[8];
        #pragma unroll
        for (int d = 0; d < 8; d++) { float2 f = __half22float2(a1[d]); r[d] = f.x + f.y; }
        g_A[(base + q1)*2    ] = make_float4(r[0], r[1], r[2], r[3]);
        g_A[(base + q1)*2 + 1] = make_float4(r[4], r[5], r[6], r[7]);
    }
    {
        float2 lf = __half22float2(l22);
        g_L[base + q2] = lf.x + lf.y;
        float r[8];
        #pragma unroll
        for (int d = 0; d < 8; d++) { float2 f = __half22float2(a2[d]); r[d] = f.x + f.y; }
        g_A[(base + q2)*2    ] = make_float4(r[0], r[1], r[2], r[3]);
        g_A[(base + q2)*2 + 1] = make_float4(r[4], r[5], r[6], r[7]);
    }
}

// ---------------- combine + projection, 4-way head-split (round-12) -----------
__global__ __launch_bounds__(192)
void proj_kernel(const float* __restrict__ pw,  // [G][DV][DV]
                 const float* __restrict__ pb)  // [G][DV]
{
    const int b = blockIdx.x, g = blockIdx.y, hwc = blockIdx.z;  // z: 0..11
    const int tid = threadIdx.x;
    const int px  = tid >> 2;          // 0..47 local pixel
    const int n   = tid & 3;           // head slot
    const int hw  = hwc*48 + px;

    __shared__ float ws[DV*DV];        // [dout][di]
    __shared__ float sav[48][DV + 1];  // +1 pad
    for (int i = tid; i < DV*DV; i += 192) ws[i] = pw[g*DV*DV + i];

    const int head = (b*GG + g)*NHN + n;
    const int qi = head*HWN + hw;
    float l = 0.f;
    float4 s0 = make_float4(0.f,0.f,0.f,0.f);
    float4 s1 = make_float4(0.f,0.f,0.f,0.f);
    #pragma unroll
    for (int kcc = 0; kcc < KC; kcc++) {
        int idx = kcc*HEADS*HWN + qi;
        l += g_L[idx];
        float4 t0 = g_A[idx*2], t1 = g_A[idx*2 + 1];
        s0.x += t0.x; s0.y += t0.y; s0.z += t0.z; s0.w += t0.w;
        s1.x += t1.x; s1.y += t1.y; s1.z += t1.z; s1.w += t1.w;
    }
    float inv = 1.f / l;
    sav[px][n*8 + 0] = s0.x*inv; sav[px][n*8 + 1] = s0.y*inv;
    sav[px][n*8 + 2] = s0.z*inv; sav[px][n*8 + 3] = s0.w*inv;
    sav[px][n*8 + 4] = s1.x*inv; sav[px][n*8 + 5] = s1.y*inv;
    sav[px][n*8 + 6] = s1.z*inv; sav[px][n*8 + 7] = s1.w*inv;
    __syncthreads();

    const float* avp = sav[px];
    #pragma unroll
    for (int dd = 0; dd < 8; dd++) {
        int dout = n*8 + dd;
        float o = __ldg(pb + g*DV + dout);
        const float* wrow = &ws[dout*DV];
        #pragma unroll
        for (int di = 0; di < DV; di++) o = fmaf(avp[di], wrow[di], o);
        g_attnp[((b*GG + g)*DV + dout)*HWN + hw] = o;
    }
}

// ---------------- LSTM gates ------------------------------------------------
__device__ __forceinline__ float sigmf(float x) { return 1.f / (1.f + __expf(-x)); }

__global__ __launch_bounds__(576)
void gates_kernel(const float* __restrict__ c_in,
                  const float* __restrict__ Wci,
                  const float* __restrict__ Wcf,
                  const float* __restrict__ Wco,
                  float* __restrict__ out)
{
    const int b  = blockIdx.x >> 6;
    const int ch = blockIdx.x & 63;
    const int hw = threadIdx.x;

    float pre[GG];
    #pragma unroll
    for (int g = 0; g < GG; g++) {
        float x = g_xg[((b*GG + g)*CH + ch)*HWN + hw];
        float y = (ch < 32) ? g_co[((b*GG + g)*(CH-DV) + ch)*HWN + hw]
                            : g_attnp[((b*GG + g)*DV + (ch - 32))*HWN + hw];
        pre[g] = x + y;
    }

    float c  = __ldg(c_in + (b*CH + ch)*HWN + hw);
    float ci = __ldg(Wci + ch*HWN + hw);
    float cf = __ldg(Wcf + ch*HWN + hw);
    float co = __ldg(Wco + ch*HWN + hw);

    float i_t = sigmf(pre[0] + c*ci);
    float f_t = sigmf(pre[1] + c*cf + 1.0f);
    float c_t = f_t*c + i_t*tanhf(pre[2]);
    float o_t = sigmf(pre[3] + c_t*co);
    float h_t = o_t*tanhf(c_t);

    const int idx = (b*CH + ch)*HWN + hw;
    out[idx] = h_t;
    out[BB*CH*HWN + idx] = c_t;
}

// ---------------- launcher ---------------------------------------------------
extern "C" void kernel_launch(void* const* d_in, const int* in_sizes, int n_in,
                              void* d_out, int out_size)
{
    const float* inputs  = (const float*)d_in[0];
    const float* rep     = (const float*)d_in[1];
    const float* c_in    = (const float*)d_in[2];
    const float* history = (const float*)d_in[3];
    const float* Wx_w    = (const float*)d_in[4];
    const float* Wx_b    = (const float*)d_in[5];
    const float* conv_w  = (const float*)d_in[6];
    const float* conv_b  = (const float*)d_in[7];
    const float* q_w     = (const float*)d_in[8];
    const float* q_b     = (const float*)d_in[9];
    const float* kv_w    = (const float*)d_in[10];
    const float* kv_b    = (const float*)d_in[11];
    const float* proj_w  = (const float*)d_in[12];
    const float* proj_b  = (const float*)d_in[13];
    const float* Wci     = (const float*)d_in[14];
    const float* Wcf     = (const float*)d_in[15];
    const float* Wco     = (const float*)d_in[16];
    float* out = (float*)d_out;
    (void)in_sizes; (void)n_in; (void)out_size;

    // projections first (attention is the critical path)
    q_tiled_kernel<<<dim3(BB*GG, 4), 288>>>(rep, q_w, q_b);
    kv_tiled_kernel<<<dim3(TT*4, BB*GG, 2), 288>>>(history, kv_w, kv_b);
    // attention (half2 key-pairs, partials over 9 key chunks)
    attn_kernel<<<dim3(HEADS, KC), ATTN_THREADS>>>();
    // convs (round-6 proven form)
    conv4g_kernel<CIN, CH, 0><<<dim3(CH, BB), 288>>>(inputs, Wx_w, Wx_b);
    conv4g_kernel<CH, CH-DV, 1><<<dim3(CH-DV, BB), 288>>>(rep, conv_w, conv_b);
    // combine + projection (4-way head split)
    proj_kernel<<<dim3(BB, GG, 12), 192>>>(proj_w, proj_b);
    // LSTM gates -> h_t, c_t
    gates_kernel<<<BB*CH, HWN>>>(c_in, Wci, Wcf, Wco, out);
}

// round 15
// speedup vs baseline: 1.4519x; 1.0109x over previous
#include <cuda_runtime.h>
#include <cuda_fp16.h>
#include <math.h>

// Problem constants
#define BB   4
#define CIN  32
#define CH   64
#define HH   24
#define WW   24
#define HWN  576          // 24*24
#define TT   5
#define DK   32
#define DV   32
#define NHN  4
#define GG   4
#define HEADS 64          // B*G*NH
#define TKEYS 2880        // T*HW
#define NPAIRS 1440       // key pairs per head
#define KC    9           // key chunks
#define KPC   320         // keys per chunk
#define PPC   160         // key-pairs per chunk
#define ATTN_THREADS 192  // 3 queries per thread

// ---------------- scratch (device globals; no allocation allowed) -------------
__device__ float   g_xg[BB*GG*CH*HWN];       // conv on inputs, 4 gates x 64 ch
__device__ float   g_co[BB*GG*(CH-DV)*HWN];  // conv on rep, 4 gates x 32 ch
__device__ __half  g_qh[HEADS*HWN*8];        // Q [head][q][8] half (scaled log2e/sqrt8)
__device__ __half2 g_Kh[HEADS*NPAIRS*8];     // K [head][pair][dim] = (k_j0, k_j1)
__device__ __half2 g_Vh[HEADS*NPAIRS*8];     // V same layout
__device__ float   g_L[KC*HEADS*HWN];        // partial exp-sums (fp32)
__device__ float4  g_A[KC*HEADS*HWN*2];      // partial weighted V sums (fp32)
__device__ float   g_attnp[BB*GG*DV*HWN];    // projected attention

// ---------------- conv: 4 gates, ADJACENT pixel pair per thread ---------------
// p0 = 2*tid (x even), p1 = p0+1: halos overlap into a 3x4 window ->
// 12 loads + 72 FMA per ic (was 18 loads). FMA order per pixel unchanged.
template<int IC, int OC, int WHICH>
__global__ __launch_bounds__(288)
void conv4g_kernel(const float* __restrict__ in,   // [B][IC][24][24]
                   const float* __restrict__ w,    // [G][OC][IC][3][3]
                   const float* __restrict__ bias) // [G][OC]
{
    const int oc = blockIdx.x;
    const int b  = blockIdx.y;
    const int tid = threadIdx.x;

    __shared__ float ws[GG*IC*9];
    for (int i = tid; i < GG*IC*9; i += 288) {
        int g = i / (IC*9);
        int r = i - g*(IC*9);
        ws[i] = w[(g*OC + oc)*IC*9 + r];
    }
    __syncthreads();

    const int p0 = tid*2, p1 = p0 + 1;
    const int y0 = p0 / WW, x0 = p0 % WW;    // x0 even, x0+1 <= 23

    float acc0[GG], acc1[GG];
    #pragma unroll
    for (int g = 0; g < GG; g++) {
        float bv = __ldg(bias + g*OC + oc);
        acc0[g] = bv; acc1[g] = bv;
    }

    const bool cL = (x0 > 0);        // col x0-1 valid
    const bool cR = (x0 < WW - 2);   // col x0+2 valid

    for (int ic = 0; ic < IC; ic++) {
        const float* ip = in + (b*IC + ic)*HWN;
        float v[3][4];
        #pragma unroll
        for (int r = 0; r < 3; r++) {
            int iy = y0 + r - 1;
            bool ry = (iy >= 0 && iy < HH);
            const float* rp = ip + iy*WW;
            v[r][0] = (ry && cL) ? __ldg(rp + x0 - 1) : 0.f;
            v[r][1] = ry ? __ldg(rp + x0)     : 0.f;
            v[r][2] = ry ? __ldg(rp + x0 + 1) : 0.f;
            v[r][3] = (ry && cR) ? __ldg(rp + x0 + 2) : 0.f;
        }
        #pragma unroll
        for (int g = 0; g < GG; g++) {
            const float* wp = &ws[(g*IC + ic)*9];
            #pragma unroll
            for (int r = 0; r < 3; r++) {
                acc0[g] = fmaf(v[r][0], wp[r*3+0], acc0[g]);
                acc0[g] = fmaf(v[r][1], wp[r*3+1], acc0[g]);
                acc0[g] = fmaf(v[r][2], wp[r*3+2], acc0[g]);
                acc1[g] = fmaf(v[r][1], wp[r*3+0], acc1[g]);
                acc1[g] = fmaf(v[r][2], wp[r*3+1], acc1[g]);
                acc1[g] = fmaf(v[r][3], wp[r*3+2], acc1[g]);
            }
        }
    }
    float* out = (WHICH == 0) ? g_xg : g_co;
    #pragma unroll
    for (int g = 0; g < GG; g++) {
        out[((b*GG + g)*OC + oc)*HWN + p0] = acc0[g];
        out[((b*GG + g)*OC + oc)*HWN + p1] = acc1[g];
    }
}

// ---------------- KV projection -> half2 key-pair layout ----------------------
__global__ __launch_bounds__(288)
void kv_tiled_kernel(const float* __restrict__ hist, // [B][T][CH][HW]
                     const float* __restrict__ kvw,  // [G][DK+DV][CH]
                     const float* __restrict__ kvb)  // [G][DK+DV]
{
    const int t    = blockIdx.x >> 2;
    const int pc   = blockIdx.x & 3;
    const int b    = blockIdx.y >> 2;
    const int g    = blockIdx.y & 3;
    const int half = blockIdx.z;
    const int tid  = threadIdx.x;
    const int og   = tid & 3;
    const int pg   = tid >> 2;          // 0..71

    __shared__ float wt[CH*32];         // [c][e] transposed
    __shared__ float bs[32];
    for (int i = tid; i < CH*32; i += 288) {
        int e = i & 31, c = i >> 5;
        wt[c*32 + e] = kvw[(g*(DK+DV) + half*32 + e)*CH + c];
    }
    if (tid < 32) bs[tid] = kvb[g*(DK+DV) + half*32 + tid];
    __syncthreads();

    float acc[8][2];
    #pragma unroll
    for (int o = 0; o < 8; o++) { acc[o][0] = 0.f; acc[o][1] = 0.f; }

    const int pxbase = pc*144 + pg*2;
    const float* hb = hist + ((b*TT + t)*CH)*HWN + pxbase;
    #pragma unroll 4
    for (int c = 0; c < CH; c++) {
        float2 px = *(const float2*)(hb + c*HWN);
        float4 w0 = *(const float4*)(&wt[c*32 + og*8]);
        float4 w1 = *(const float4*)(&wt[c*32 + og*8 + 4]);
        float wv[8] = {w0.x, w0.y, w0.z, w0.w, w1.x, w1.y, w1.z, w1.w};
        #pragma unroll
        for (int o = 0; o < 8; o++) {
            acc[o][0] = fmaf(wv[o], px.x, acc[o][0]);
            acc[o][1] = fmaf(wv[o], px.y, acc[o][1]);
        }
    }

    const int head = (b*GG + g)*NHN + og;
    const int jp = (t*HWN + pxbase) >> 1;   // key-pair index (pxbase is even)
    __half2* dst = ((half == 0) ? g_Kh : g_Vh) + (head*NPAIRS + jp)*8;
    #pragma unroll
    for (int o = 0; o < 8; o++) {
        float bb = bs[og*8 + o];
        dst[o] = __floats2half2_rn(acc[o][0] + bb, acc[o][1] + bb);
    }
}

// ---------------- Q projection -> half, scale folds log2e/sqrt8 ---------------
__global__ __launch_bounds__(288)
void q_tiled_kernel(const float* __restrict__ rep,  // [B][CH][HW]
                    const float* __restrict__ qw,   // [G][DK][CH]
                    const float* __restrict__ qb)   // [G][DK]
{
    const int b     = blockIdx.x >> 2;
    const int g     = blockIdx.x & 3;
    const int chunk = blockIdx.y;       // 4 chunks of 144 px
    const int tid   = threadIdx.x;
    const int og    = tid & 3;
    const int pg    = tid >> 2;         // 0..71
    const int px0   = chunk*144 + pg*2;

    __shared__ float wt[CH*32];
    __shared__ float bs[32];
    for (int i = tid; i < CH*32; i += 288) {
        int e = i & 31, c = i >> 5;
        wt[c*32 + e] = qw[(g*DK + e)*CH + c];
    }
    if (tid < 32) bs[tid] = qb[g*DK + tid];
    __syncthreads();

    float acc[8][2];
    #pragma unroll
    for (int o = 0; o < 8; o++) { acc[o][0] = 0.f; acc[o][1] = 0.f; }

    const float* rb = rep + (b*CH)*HWN + px0;
    #pragma unroll 4
    for (int c = 0; c < CH; c++) {
        float2 px = *(const float2*)(rb + c*HWN);
        float4 w0 = *(const float4*)(&wt[c*32 + og*8]);
        float4 w1 = *(const float4*)(&wt[c*32 + og*8 + 4]);
        float wv[8] = {w0.x, w0.y, w0.z, w0.w, w1.x, w1.y, w1.z, w1.w};
        #pragma unroll
        for (int o = 0; o < 8; o++) {
            acc[o][0] = fmaf(wv[o], px.x, acc[o][0]);
            acc[o][1] = fmaf(wv[o], px.y, acc[o][1]);
        }
    }

    const float scale = 0.51006972f;    // log2(e)/sqrt(8): softmax via exp2
    const int head = (b*GG + g)*NHN + og;
    float bb[8];
    #pragma unroll
    for (int o = 0; o < 8; o++) bb[o] = bs[og*8 + o];
    __half* dst = g_qh + (head*HWN + px0)*8;
    #pragma unroll
    for (int p = 0; p < 2; p++)
        #pragma unroll
        for (int o = 0; o < 8; o++)
            dst[p*8 + o] = __float2half((acc[o][p] + bb[o])*scale);
}

// ---------------- attention: half2 key-pairs, HFMA2, h2exp2 -------------------
__global__ __launch_bounds__(ATTN_THREADS)
void attn_kernel()
{
    const int head = blockIdx.x;       // 0..63
    const int kc   = blockIdx.y;       // 0..8
    const int tid  = threadIdx.x;

    const int q0 = tid, q1 = tid + 192, q2 = tid + 384;

    __half2 Q0[8], Q1[8], Q2[8];
    {
        uint4 v0 = __ldg((const uint4*)(g_qh + (head*HWN + q0)*8));
        uint4 v1 = __ldg((const uint4*)(g_qh + (head*HWN + q1)*8));
        uint4 v2 = __ldg((const uint4*)(g_qh + (head*HWN + q2)*8));
        const __half* h0 = (const __half*)&v0;
        const __half* h1 = (const __half*)&v1;
        const __half* h2 = (const __half*)&v2;
        #pragma unroll
        for (int d = 0; d < 8; d++) {
            Q0[d] = __half2half2(h0[d]);
            Q1[d] = __half2half2(h1[d]);
            Q2[d] = __half2half2(h2[d]);
        }
    }

    const uint4* Kp = (const uint4*)(g_Kh + (head*NPAIRS + kc*PPC)*8);
    const uint4* Vp = (const uint4*)(g_Vh + (head*NPAIRS + kc*PPC)*8);

    __half2 l20 = __float2half2_rn(0.f);
    __half2 l21 = l20, l22 = l20;
    __half2 a0[8], a1[8], a2[8];
    #pragma unroll
    for (int d = 0; d < 8; d++) { a0[d] = l20; a1[d] = l20; a2[d] = l20; }

    #pragma unroll 2
    for (int jp = 0; jp < PPC; jp++) {
        uint4 ka = __ldg(Kp + jp*2);
        uint4 kb = __ldg(Kp + jp*2 + 1);
        const __half2* k0 = (const __half2*)&ka;   // dims 0..3
        const __half2* k1 = (const __half2*)&kb;   // dims 4..7

        __half2 s0 = __hmul2(Q0[0], k0[0]);
        __half2 s1 = __hmul2(Q1[0], k0[0]);
        __half2 s2 = __hmul2(Q2[0], k0[0]);
        #pragma unroll
        for (int d = 1; d < 4; d++) {
            s0 = __hfma2(Q0[d], k0[d], s0);
            s1 = __hfma2(Q1[d], k0[d], s1);
            s2 = __hfma2(Q2[d], k0[d], s2);
        }
        #pragma unroll
        for (int d = 0; d < 4; d++) {
            s0 = __hfma2(Q0[4+d], k1[d], s0);
            s1 = __hfma2(Q1[4+d], k1[d], s1);
            s2 = __hfma2(Q2[4+d], k1[d], s2);
        }

        __half2 p0 = h2exp2(s0);   // Q pre-scaled by log2e -> true exp
        __half2 p1 = h2exp2(s1);
        __half2 p2 = h2exp2(s2);
        l20 = __hadd2(l20, p0);
        l21 = __hadd2(l21, p1);
        l22 = __hadd2(l22, p2);

        uint4 va = __ldg(Vp + jp*2);
        uint4 vb = __ldg(Vp + jp*2 + 1);
        const __half2* v0 = (const __half2*)&va;
        const __half2* v1 = (const __half2*)&vb;
        #pragma unroll
        for (int d = 0; d < 4; d++) {
            a0[d]   = __hfma2(p0, v0[d], a0[d]);
            a1[d]   = __hfma2(p1, v0[d], a1[d]);
            a2[d]   = __hfma2(p2, v0[d], a2[d]);
            a0[4+d] = __hfma2(p0, v1[d], a0[4+d]);
            a1[4+d] = __hfma2(p1, v1[d], a1[4+d]);
            a2[4+d] = __hfma2(p2, v1[d], a2[4+d]);
        }
    }

    const int base = (kc*HEADS + head)*HWN;
    {
        float2 lf = __half22float2(l20);
        g_L[base + q0] = lf.x + lf.y;
        float r[8];
        #pragma unroll
        for (int d = 0; d < 8; d++) { float2 f = __half22float2(a0[d]); r[d] = f.x + f.y; }
        g_A[(base + q0)*2    ] = make_float4(r[0], r[1], r[2], r[3]);
        g_A[(base + q0)*2 + 1] = make_float4(r[4], r[5], r[6], r[7]);
    }
    {
        float2 lf = __half22float2(l21);
        g_L[base + q1] = lf.x + lf.y;
        float r[8];
        #pragma unroll
        for (int d = 0; d < 8; d++) { float2 f = __half22float2(a1[d]); r[d] = f.x + f.y; }
        g_A[(base + q1)*2    ] = make_float4(r[0], r[1], r[2], r[3]);
        g_A[(base + q1)*2 + 1] = make_float4(r[4], r[5], r[6], r[7]);
    }
    {
        float2 lf = __half22float2(l22);
        g_L[base + q2] = lf.x + lf.y;
        float r[8];
        #pragma unroll
        for (int d = 0; d < 8; d++) { float2 f = __half22float2(a2[d]); r[d] = f.x + f.y; }
        g_A[(base + q2)*2    ] = make_float4(r[0], r[1], r[2], r[3]);
        g_A[(base + q2)*2 + 1] = make_float4(r[4], r[5], r[6], r[7]);
    }
}

// ---------------- combine + projection, 4-way head-split (round-12) -----------
__global__ __launch_bounds__(192)
void proj_kernel(const float* __restrict__ pw,  // [G][DV][DV]
                 const float* __restrict__ pb)  // [G][DV]
{
    const int b = blockIdx.x, g = blockIdx.y, hwc = blockIdx.z;  // z: 0..11
    const int tid = threadIdx.x;
    const int px  = tid >> 2;          // 0..47 local pixel
    const int n   = tid & 3;           // head slot
    const int hw  = hwc*48 + px;

    __shared__ float ws[DV*DV];        // [dout][di]
    __shared__ float sav[48][DV + 1];  // +1 pad
    for (int i = tid; i < DV*DV; i += 192) ws[i] = pw[g*DV*DV + i];

    const int head = (b*GG + g)*NHN + n;
    const int qi = head*HWN + hw;
    float l = 0.f;
    float4 s0 = make_float4(0.f,0.f,0.f,0.f);
    float4 s1 = make_float4(0.f,0.f,0.f,0.f);
    #pragma unroll
    for (int kcc = 0; kcc < KC; kcc++) {
        int idx = kcc*HEADS*HWN + qi;
        l += g_L[idx];
        float4 t0 = g_A[idx*2], t1 = g_A[idx*2 + 1];
        s0.x += t0.x; s0.y += t0.y; s0.z += t0.z; s0.w += t0.w;
        s1.x += t1.x; s1.y += t1.y; s1.z += t1.z; s1.w += t1.w;
    }
    float inv = 1.f / l;
    sav[px][n*8 + 0] = s0.x*inv; sav[px][n*8 + 1] = s0.y*inv;
    sav[px][n*8 + 2] = s0.z*inv; sav[px][n*8 + 3] = s0.w*inv;
    sav[px][n*8 + 4] = s1.x*inv; sav[px][n*8 + 5] = s1.y*inv;
    sav[px][n*8 + 6] = s1.z*inv; sav[px][n*8 + 7] = s1.w*inv;
    __syncthreads();

    const float* avp = sav[px];
    #pragma unroll
    for (int dd = 0; dd < 8; dd++) {
        int dout = n*8 + dd;
        float o = __ldg(pb + g*DV + dout);
        const float* wrow = &ws[dout*DV];
        #pragma unroll
        for (int di = 0; di < DV; di++) o = fmaf(avp[di], wrow[di], o);
        g_attnp[((b*GG + g)*DV + dout)*HWN + hw] = o;
    }
}

// ---------------- LSTM gates ------------------------------------------------
__device__ __forceinline__ float sigmf(float x) { return 1.f / (1.f + __expf(-x)); }

__global__ __launch_bounds__(576)
void gates_kernel(const float* __restrict__ c_in,
                  const float* __restrict__ Wci,
                  const float* __restrict__ Wcf,
                  const float* __restrict__ Wco,
                  float* __restrict__ out)
{
    const int b  = blockIdx.x >> 6;
    const int ch = blockIdx.x & 63;
    const int hw = threadIdx.x;

    float pre[GG];
    #pragma unroll
    for (int g = 0; g < GG; g++) {
        float x = g_xg[((b*GG + g)*CH + ch)*HWN + hw];
        float y = (ch < 32) ? g_co[((b*GG + g)*(CH-DV) + ch)*HWN + hw]
                            : g_attnp[((b*GG + g)*DV + (ch - 32))*HWN + hw];
        pre[g] = x + y;
    }

    float c  = __ldg(c_in + (b*CH + ch)*HWN + hw);
    float ci = __ldg(Wci + ch*HWN + hw);
    float cf = __ldg(Wcf + ch*HWN + hw);
    float co = __ldg(Wco + ch*HWN + hw);

    float i_t = sigmf(pre[0] + c*ci);
    float f_t = sigmf(pre[1] + c*cf + 1.0f);
    float c_t = f_t*c + i_t*tanhf(pre[2]);
    float o_t = sigmf(pre[3] + c_t*co);
    float h_t = o_t*tanhf(c_t);

    const int idx = (b*CH + ch)*HWN + hw;
    out[idx] = h_t;
    out[BB*CH*HWN + idx] = c_t;
}

// ---------------- launcher ---------------------------------------------------
extern "C" void kernel_launch(void* const* d_in, const int* in_sizes, int n_in,
                              void* d_out, int out_size)
{
    const float* inputs  = (const float*)d_in[0];
    const float* rep     = (const float*)d_in[1];
    const float* c_in    = (const float*)d_in[2];
    const float* history = (const float*)d_in[3];
    const float* Wx_w    = (const float*)d_in[4];
    const float* Wx_b    = (const float*)d_in[5];
    const float* conv_w  = (const float*)d_in[6];
    const float* conv_b  = (const float*)d_in[7];
    const float* q_w     = (const float*)d_in[8];
    const float* q_b     = (const float*)d_in[9];
    const float* kv_w    = (const float*)d_in[10];
    const float* kv_b    = (const float*)d_in[11];
    const float* proj_w  = (const float*)d_in[12];
    const float* proj_b  = (const float*)d_in[13];
    const float* Wci     = (const float*)d_in[14];
    const float* Wcf     = (const float*)d_in[15];
    const float* Wco     = (const float*)d_in[16];
    float* out = (float*)d_out;
    (void)in_sizes; (void)n_in; (void)out_size;

    // projections first (attention is the critical path)
    q_tiled_kernel<<<dim3(BB*GG, 4), 288>>>(rep, q_w, q_b);
    kv_tiled_kernel<<<dim3(TT*4, BB*GG, 2), 288>>>(history, kv_w, kv_b);
    // attention (half2 key-pairs, partials over 9 key chunks)
    attn_kernel<<<dim3(HEADS, KC), ATTN_THREADS>>>();
    // convs (adjacent-pixel pair: 12 loads / 72 FMA per ic)
    conv4g_kernel<CIN, CH, 0><<<dim3(CH, BB), 288>>>(inputs, Wx_w, Wx_b);
    conv4g_kernel<CH, CH-DV, 1><<<dim3(CH-DV, BB), 288>>>(rep, conv_w, conv_b);
    // combine + projection (4-way head split)
    proj_kernel<<<dim3(BB, GG, 12), 192>>>(proj_w, proj_b);
    // LSTM gates -> h_t, c_t
    gates_kernel<<<BB*CH, HWN>>>(c_in, Wci, Wcf, Wco, out);
}